// round 14
// baseline (speedup 1.0000x reference)
#include <cuda_runtime.h>
#include <cuda_fp16.h>
#include <math_constants.h>
#include <cstdint>

// ---------------------------------------------------------------- constants
#define NN 64
#define CC 3
#define NCC (NN*CC)        // 192 rows
#define LL 4096
#define KK 128             // shapelets
#define SS 64              // shapelet length
#define WW (LL - SS + 1)   // 4033 valid windows
#define TPR 64             // window tiles (of 64) per row
#define TTOT (NCC*TPR)     // 12288 tiles
#define GRID 296           // 2 CTAs x 148 SMs, single wave
#define TMAIN 256

#define XSN 2768           // strip f32 (42*64+64, + pad)
#define PSN 1472           // parity words (42*32+32, + prefetch overrun pad)
#define NGN 1440           // window pairs (42*32, + prefetch overrun pad)

// ---------------------------------------------------------------- scratch
__device__ int g_minb[NN*KK];   // running min d^2 (int bits); re-inited each launch
__device__ int g_ictr;          // init counter   (zero-init; finalize resets)
__device__ int g_ctr;           // finish counter (zero-init; finalize resets)

__device__ __forceinline__ uint32_t packh(float a, float b) {
    __half2 h = __floats2half2_rn(a, b);
    return *(uint32_t*)&h;
}

// ---------------------------------------------------------------- mma wrappers (f16 accum)
__device__ __forceinline__ void mma16816_h(uint32_t& c0, uint32_t& c1,
                                           uint32_t a0, uint32_t a1, uint32_t a2, uint32_t a3,
                                           uint32_t b0, uint32_t b1) {
    asm("mma.sync.aligned.m16n8k16.row.col.f16.f16.f16.f16 "
        "{%0,%1}, {%2,%3,%4,%5}, {%6,%7}, {%0,%1};"
        : "+r"(c0), "+r"(c1)
        : "r"(a0), "r"(a1), "r"(a2), "r"(a3), "r"(b0), "r"(b1));
}
__device__ __forceinline__ void mma16816_hs(uint32_t& c0, uint32_t& c1,
                                            uint32_t a0, uint32_t a1, uint32_t a2, uint32_t a3,
                                            uint32_t b0, uint32_t b1, uint32_t seed) {
    asm("mma.sync.aligned.m16n8k16.row.col.f16.f16.f16.f16 "
        "{%0,%1}, {%2,%3,%4,%5}, {%6,%7}, {%8,%8};"
        : "=r"(c0), "=r"(c1)
        : "r"(a0), "r"(a1), "r"(a2), "r"(a3), "r"(b0), "r"(b1), "r"(seed));
}

// ---------------------------------------------------------------- main (single launch)
// Persistent static split (12288 tiles over 296 CTAs, single wave).
// Fully fused with register-disciplined prologue (bounded unrolls keep LDG
// live-ranges short; main loop identical to the 52us R12 core).
__global__ __launch_bounds__(TMAIN, 2) void main_kernel(const float* __restrict__ x,
                                                        const float* __restrict__ sh,
                                                        float* __restrict__ out) {
    __shared__ float xs[XSN];
    __shared__ uint32_t SE[PSN], SO[PSN];
    __shared__ uint32_t negx2h[NGN];
    __shared__ uint32_t As[KK * 33];
    __shared__ float s2s[KK];

    int bi = blockIdx.x;
    int tid = threadIdx.x, lane = tid & 31, warp = tid >> 5;
    int wm = warp & 3, wn = warp >> 2;
    int q = lane & 3, g = lane >> 2;

    // ---- per-CTA minb slice init (28 entries each; 296*28 >= 8192)
    {
        int i0 = bi * 28 + tid;
        if (tid < 28 && i0 < NN * KK) g_minb[i0] = 0x7F800000;  // +inf
        __threadfence();
        __syncthreads();
        if (tid == 0) atomicAdd(&g_ictr, 1);
    }

    int js = (int)(((long long)bi * TTOT) / GRID);
    int je = (int)(((long long)(bi + 1) * TTOT) / GRID);

    while (js < je) {
        int row = js >> 6;                 // nc row
        int t0 = js & 63;
        int run = min(64 - t0, je - js);
        int c = row % CC, n = row / CC;
        int wbase = t0 * 64;               // first window of run within row
        int nelem = run * 64 + 64;
        int nW = run * 64;
        const float* xr = x + row * LL;
        const float* shc = sh + c * (KK * SS);

        __syncthreads();   // prior run's smem readers done

        // 1) pack shapelet tile (channel c) from gmem (coalesced float2/lane)
#pragma unroll 1
        for (int i = tid; i < KK * 32; i += TMAIN) {
            int k = i >> 5, j = i & 31;
            const float2 p = *(const float2*)(shc + k * SS + j * 2);
            As[k * 33 + j] = packh(p.x, p.y);
        }
        // 1b) s2 per k-row (f32 exact; bounded unroll keeps LDG live-range short)
        if (tid < KK) {
            const float* p = shc + tid * SS;
            float s = 0.f;
#pragma unroll 4
            for (int j = 0; j < SS; j++) s = fmaf(p[j], p[j], s);
            s2s[tid] = s;
        }
        // 2) f32 strip (zero-padded past row end)
#pragma unroll 1
        for (int i = tid; i < nelem + 8; i += TMAIN) {
            int gi = wbase + i;
            xs[i] = (gi < LL) ? xr[gi] : 0.f;
        }
        __syncthreads();

        // 3) fp16 parity packs (pad region zeroed for prefetch overrun)
        {
            int np = run * 32 + 32;
#pragma unroll 1
            for (int i = tid; i < np; i += TMAIN) {
                float e0 = xs[2 * i], e1 = xs[2 * i + 1], e2 = xs[2 * i + 2];
                SE[i] = packh(e0, e1);
                SO[i] = packh(e1, e2);
            }
            for (int i = np + tid; i < PSN; i += TMAIN) { SE[i] = 0u; SO[i] = 0u; }
            for (int i = run * 32 + tid; i < NGN; i += TMAIN) negx2h[i] = 0u;
        }
        // 4) window norms (sliding update), stored as packed {-x2/2} f16 pairs
        {
            int ws = ((run + 7) >> 3) * 2;         // even windows/thread
            int w0 = tid * ws;
            if (w0 < nW) {
                float s = 0.f;
#pragma unroll 16
                for (int i = 0; i < SS; i++) { float v = xs[w0 + i]; s = fmaf(v, v, s); }
                float pv = (wbase + w0 < WW) ? -0.5f * s : -CUDART_INF_F;
#pragma unroll 1
                for (int r = 1; r < ws; r++) {
                    int w = w0 + r;
                    float vin = xs[w + SS - 1], vout = xs[w - 1];
                    s = fmaf(vin, vin, fmaf(-vout, vout, s));
                    float cv = (w < nW && wbase + w < WW) ? -0.5f * s : -CUDART_INF_F;
                    if (r & 1) negx2h[(w0 + r) >> 1] = packh(pv, cv);
                    pv = cv;
                }
            }
        }
        __syncthreads();

        // 5) A fragments + s2 (rows wm*32 .. wm*32+31)
        uint32_t A[2][4][4];
        float s2v[2][2];
#pragma unroll
        for (int mt = 0; mt < 2; mt++) {
            int r0 = wm * 32 + mt * 16 + g;
            int r1 = r0 + 8;
            const uint32_t* ap0 = As + r0 * 33;
            const uint32_t* ap1 = As + r1 * 33;
#pragma unroll
            for (int ks = 0; ks < 4; ks++) {
                A[mt][ks][0] = ap0[ks * 8 + q];
                A[mt][ks][1] = ap1[ks * 8 + q];
                A[mt][ks][2] = ap0[ks * 8 + q + 4];
                A[mt][ks][3] = ap1[ks * 8 + q + 4];
            }
            s2v[mt][0] = s2s[r0];
            s2v[mt][1] = s2s[r1];
        }

        const uint32_t* sp = ((g & 1) ? SO : SE) + (g >> 1) + q + wn * 16;
        const uint32_t* seedp = negx2h + wn * 16 + q;

        const __half2 NEGINF2 = __half2half2(__float2half(-CUDART_INF_F));
        __half2 mn2[2][2] = {{NEGINF2, NEGINF2}, {NEGINF2, NEGINF2}};

        // prime B words + seeds for tile 0
        uint32_t Bw[11], Sd[4];
#pragma unroll
        for (int j = 0; j < 11; j++) Bw[j] = sp[j * 4];
#pragma unroll
        for (int j = 0; j < 4; j++) Sd[j] = seedp[j * 4];

#pragma unroll 1
        for (int t = 0; t < run; t++) {
            uint32_t C[2][4][2];   // [mt][nt][half] -- 8 serial K-chains

            // ks = 0: seed with -x2/2
#pragma unroll
            for (int nt = 0; nt < 4; nt++) {
                mma16816_hs(C[0][nt][0], C[0][nt][1],
                            A[0][0][0], A[0][0][1], A[0][0][2], A[0][0][3],
                            Bw[nt], Bw[nt + 1], Sd[nt]);
                mma16816_hs(C[1][nt][0], C[1][nt][1],
                            A[1][0][0], A[1][0][1], A[1][0][2], A[1][0][3],
                            Bw[nt], Bw[nt + 1], Sd[nt]);
            }
            // ks = 1..3 accumulate into the same chains (ks-outer: ILP = 8)
#pragma unroll
            for (int ks = 1; ks < 4; ks++)
#pragma unroll
                for (int nt = 0; nt < 4; nt++) {
                    mma16816_h(C[0][nt][0], C[0][nt][1],
                               A[0][ks][0], A[0][ks][1], A[0][ks][2], A[0][ks][3],
                               Bw[nt + 2 * ks], Bw[nt + 2 * ks + 1]);
                    mma16816_h(C[1][nt][0], C[1][nt][1],
                               A[1][ks][0], A[1][ks][1], A[1][ks][2], A[1][ks][3],
                               Bw[nt + 2 * ks], Bw[nt + 2 * ks + 1]);
                }

            // prefetch next tile's B words + seeds (overlaps HMMA drain)
#pragma unroll
            for (int j = 0; j < 11; j++) Bw[j] = sp[32 + j * 4];
#pragma unroll
            for (int j = 0; j < 4; j++) Sd[j] = seedp[32 + j * 4];
            sp += 32;
            seedp += 32;

            // single epilogue: 8 HMAX2
#pragma unroll
            for (int nt = 0; nt < 4; nt++) {
                mn2[0][0] = __hmax2(mn2[0][0], *(__half2*)&C[0][nt][0]);
                mn2[0][1] = __hmax2(mn2[0][1], *(__half2*)&C[0][nt][1]);
                mn2[1][0] = __hmax2(mn2[1][0], *(__half2*)&C[1][nt][0]);
                mn2[1][1] = __hmax2(mn2[1][1], *(__half2*)&C[1][nt][1]);
            }
        }

        // ---- init barrier before first atomicMin (expected zero wait)
        if (tid == 0) { while (atomicAdd(&g_ictr, 0) < GRID) { } }
        __syncthreads();

        // reduce: max over h2 halves, then over the 4 q-lanes sharing rows
#pragma unroll
        for (int mt = 0; mt < 2; mt++)
#pragma unroll
            for (int h = 0; h < 2; h++) {
                float2 f = __half22float2(mn2[mt][h]);
                float m = fmaxf(f.x, f.y);
                m = fmaxf(m, __shfl_xor_sync(0xFFFFFFFFu, m, 1));
                m = fmaxf(m, __shfl_xor_sync(0xFFFFFFFFu, m, 2));
                if (q == 0) {
                    int kr = wm * 32 + mt * 16 + h * 8 + g;
                    float d2 = fmaf(-2.f, m, s2v[mt][h]);
                    atomicMin(&g_minb[n * KK + kr], __float_as_int(d2));
                }
            }

        js += run;
    }

    // last CTA finalizes: sqrt(min d^2) -> out; reset counters for replay
    __shared__ int lastFlag;
    __threadfence();
    __syncthreads();
    if (tid == 0) lastFlag = (atomicAdd(&g_ctr, 1) == GRID - 1);
    __syncthreads();
    if (lastFlag) {
        __threadfence();
        for (int i = tid; i < NN * KK; i += TMAIN) {
            float d2 = __int_as_float(g_minb[i]);
            out[i] = sqrtf(fmaxf(d2, 0.f));
        }
        __threadfence();
        if (tid == 0) { g_ctr = 0; g_ictr = 0; }
    }
}

// ---------------------------------------------------------------- launch
extern "C" void kernel_launch(void* const* d_in, const int* in_sizes, int n_in,
                              void* d_out, int out_size) {
    const float* x  = (const float*)d_in[0];
    const float* sh = (const float*)d_in[1];
    if (n_in >= 2 && in_sizes[0] == CC * KK * SS && in_sizes[1] == NN * CC * LL) {
        x  = (const float*)d_in[1];
        sh = (const float*)d_in[0];
    }
    main_kernel<<<GRID, TMAIN>>>(x, sh, (float*)d_out);
}

// round 15
// speedup vs baseline: 1.1543x; 1.1543x over previous
#include <cuda_runtime.h>
#include <cuda_fp16.h>
#include <math_constants.h>
#include <cstdint>

// ---------------------------------------------------------------- constants
#define NN 64
#define CC 3
#define NCC (NN*CC)        // 192 rows
#define LL 4096
#define KK 128             // shapelets
#define SS 64              // shapelet length
#define WW (LL - SS + 1)   // 4033 valid windows
#define TPR 64             // window tiles (of 64) per row
#define TTOT (NCC*TPR)     // 12288 tiles
#define GRID 296           // 2 CTAs x 148 SMs, single wave
#define TMAIN 256

#define XSN 2768           // strip f32 (42*64+64, + pad)
#define PSN 1472           // parity words (42*32+32, + prefetch overrun pad)
#define NGN 1440           // window pairs (42*32, + prefetch overrun pad)

// ---------------------------------------------------------------- scratch
__device__ int g_minb[NN*KK];   // running min d^2 (int bits); re-inited each launch
__device__ int g_ictr;          // init counter   (zero-init; finalize resets)
__device__ int g_ctr;           // finish counter (zero-init; finalize resets)

__device__ __forceinline__ uint32_t packh(float a, float b) {
    __half2 h = __floats2half2_rn(a, b);
    return *(uint32_t*)&h;
}

// ---------------------------------------------------------------- mma wrappers (f16 accum)
__device__ __forceinline__ void mma16816_h(uint32_t& c0, uint32_t& c1,
                                           uint32_t a0, uint32_t a1, uint32_t a2, uint32_t a3,
                                           uint32_t b0, uint32_t b1) {
    asm("mma.sync.aligned.m16n8k16.row.col.f16.f16.f16.f16 "
        "{%0,%1}, {%2,%3,%4,%5}, {%6,%7}, {%0,%1};"
        : "+r"(c0), "+r"(c1)
        : "r"(a0), "r"(a1), "r"(a2), "r"(a3), "r"(b0), "r"(b1));
}
__device__ __forceinline__ void mma16816_hs(uint32_t& c0, uint32_t& c1,
                                            uint32_t a0, uint32_t a1, uint32_t a2, uint32_t a3,
                                            uint32_t b0, uint32_t b1, uint32_t seed) {
    asm("mma.sync.aligned.m16n8k16.row.col.f16.f16.f16.f16 "
        "{%0,%1}, {%2,%3,%4,%5}, {%6,%7}, {%8,%8};"
        : "=r"(c0), "=r"(c1)
        : "r"(a0), "r"(a1), "r"(a2), "r"(a3), "r"(b0), "r"(b1), "r"(seed));
}

// ---------------------------------------------------------------- main (single launch)
// Persistent static split (12288 tiles over 296 CTAs, single wave).
// Fused prologue made latency-flat: parallel s^2 (4 threads/row + shfl),
// fully-unrolled coalesced A pack. Main loop identical to the 52us R12 core.
__global__ __launch_bounds__(TMAIN, 2) void main_kernel(const float* __restrict__ x,
                                                        const float* __restrict__ sh,
                                                        float* __restrict__ out) {
    __shared__ float xs[XSN];
    __shared__ uint32_t SE[PSN], SO[PSN];
    __shared__ uint32_t negx2h[NGN];
    __shared__ uint32_t As[KK * 33];
    __shared__ float s2s[KK];

    int bi = blockIdx.x;
    int tid = threadIdx.x, lane = tid & 31, warp = tid >> 5;
    int wm = warp & 3, wn = warp >> 2;
    int q = lane & 3, g = lane >> 2;

    // ---- per-CTA minb slice init (28 entries each; 296*28 >= 8192)
    {
        int i0 = bi * 28 + tid;
        if (tid < 28 && i0 < NN * KK) g_minb[i0] = 0x7F800000;  // +inf
        __threadfence();
        __syncthreads();
        if (tid == 0) atomicAdd(&g_ictr, 1);
    }

    int js = (int)(((long long)bi * TTOT) / GRID);
    int je = (int)(((long long)(bi + 1) * TTOT) / GRID);

    while (js < je) {
        int row = js >> 6;                 // nc row
        int t0 = js & 63;
        int run = min(64 - t0, je - js);
        int c = row % CC, n = row / CC;
        int wbase = t0 * 64;               // first window of run within row
        int nelem = run * 64 + 64;
        int nW = run * 64;
        const float* xr = x + row * LL;
        const float* shc = sh + c * (KK * SS);

        __syncthreads();   // prior run's smem readers done

        // 1) pack shapelet tile (channel c) from gmem, full unroll (MLP-16)
#pragma unroll
        for (int u = 0; u < 16; u++) {
            int i = u * TMAIN + tid;
            int k = i >> 5, j = i & 31;
            const float2 p = *(const float2*)(shc + k * SS + j * 2);
            As[k * 33 + j] = packh(p.x, p.y);
        }
        // 1b) s2: 4 threads per k-row, 16 elements each (MLP-16), shfl reduce
#pragma unroll
        for (int pass = 0; pass < 2; pass++) {
            int kr = pass * 64 + (tid >> 2);
            int part = tid & 3;
            const float* p = shc + kr * SS + part * 16;
            float s = 0.f;
#pragma unroll
            for (int j = 0; j < 16; j++) s = fmaf(p[j], p[j], s);
            s += __shfl_xor_sync(0xFFFFFFFFu, s, 1);
            s += __shfl_xor_sync(0xFFFFFFFFu, s, 2);
            if (part == 0) s2s[kr] = s;
        }
        // 2) f32 strip (zero-padded past row end)
#pragma unroll 1
        for (int i = tid; i < nelem + 8; i += TMAIN) {
            int gi = wbase + i;
            xs[i] = (gi < LL) ? xr[gi] : 0.f;
        }
        __syncthreads();

        // 3) fp16 parity packs (pad region zeroed for prefetch overrun)
        {
            int np = run * 32 + 32;
#pragma unroll 1
            for (int i = tid; i < np; i += TMAIN) {
                float e0 = xs[2 * i], e1 = xs[2 * i + 1], e2 = xs[2 * i + 2];
                SE[i] = packh(e0, e1);
                SO[i] = packh(e1, e2);
            }
            for (int i = np + tid; i < PSN; i += TMAIN) { SE[i] = 0u; SO[i] = 0u; }
            for (int i = run * 32 + tid; i < NGN; i += TMAIN) negx2h[i] = 0u;
        }
        // 4) window norms (sliding update), stored as packed {-x2/2} f16 pairs
        {
            int ws = ((run + 7) >> 3) * 2;         // even windows/thread
            int w0 = tid * ws;
            if (w0 < nW) {
                float s = 0.f;
#pragma unroll
                for (int i = 0; i < SS; i++) { float v = xs[w0 + i]; s = fmaf(v, v, s); }
                float pv = (wbase + w0 < WW) ? -0.5f * s : -CUDART_INF_F;
#pragma unroll 1
                for (int r = 1; r < ws; r++) {
                    int w = w0 + r;
                    float vin = xs[w + SS - 1], vout = xs[w - 1];
                    s = fmaf(vin, vin, fmaf(-vout, vout, s));
                    float cv = (w < nW && wbase + w < WW) ? -0.5f * s : -CUDART_INF_F;
                    if (r & 1) negx2h[(w0 + r) >> 1] = packh(pv, cv);
                    pv = cv;
                }
            }
        }
        __syncthreads();

        // 5) A fragments + s2 (rows wm*32 .. wm*32+31)
        uint32_t A[2][4][4];
        float s2v[2][2];
#pragma unroll
        for (int mt = 0; mt < 2; mt++) {
            int r0 = wm * 32 + mt * 16 + g;
            int r1 = r0 + 8;
            const uint32_t* ap0 = As + r0 * 33;
            const uint32_t* ap1 = As + r1 * 33;
#pragma unroll
            for (int ks = 0; ks < 4; ks++) {
                A[mt][ks][0] = ap0[ks * 8 + q];
                A[mt][ks][1] = ap1[ks * 8 + q];
                A[mt][ks][2] = ap0[ks * 8 + q + 4];
                A[mt][ks][3] = ap1[ks * 8 + q + 4];
            }
            s2v[mt][0] = s2s[r0];
            s2v[mt][1] = s2s[r1];
        }

        const uint32_t* sp = ((g & 1) ? SO : SE) + (g >> 1) + q + wn * 16;
        const uint32_t* seedp = negx2h + wn * 16 + q;

        const __half2 NEGINF2 = __half2half2(__float2half(-CUDART_INF_F));
        __half2 mn2[2][2] = {{NEGINF2, NEGINF2}, {NEGINF2, NEGINF2}};

        // prime B words + seeds for tile 0
        uint32_t Bw[11], Sd[4];
#pragma unroll
        for (int j = 0; j < 11; j++) Bw[j] = sp[j * 4];
#pragma unroll
        for (int j = 0; j < 4; j++) Sd[j] = seedp[j * 4];

#pragma unroll 1
        for (int t = 0; t < run; t++) {
            uint32_t C[2][4][2];   // [mt][nt][half] -- 8 serial K-chains

            // ks = 0: seed with -x2/2
#pragma unroll
            for (int nt = 0; nt < 4; nt++) {
                mma16816_hs(C[0][nt][0], C[0][nt][1],
                            A[0][0][0], A[0][0][1], A[0][0][2], A[0][0][3],
                            Bw[nt], Bw[nt + 1], Sd[nt]);
                mma16816_hs(C[1][nt][0], C[1][nt][1],
                            A[1][0][0], A[1][0][1], A[1][0][2], A[1][0][3],
                            Bw[nt], Bw[nt + 1], Sd[nt]);
            }
            // ks = 1..3 accumulate into the same chains (ks-outer: ILP = 8)
#pragma unroll
            for (int ks = 1; ks < 4; ks++)
#pragma unroll
                for (int nt = 0; nt < 4; nt++) {
                    mma16816_h(C[0][nt][0], C[0][nt][1],
                               A[0][ks][0], A[0][ks][1], A[0][ks][2], A[0][ks][3],
                               Bw[nt + 2 * ks], Bw[nt + 2 * ks + 1]);
                    mma16816_h(C[1][nt][0], C[1][nt][1],
                               A[1][ks][0], A[1][ks][1], A[1][ks][2], A[1][ks][3],
                               Bw[nt + 2 * ks], Bw[nt + 2 * ks + 1]);
                }

            // prefetch next tile's B words + seeds (overlaps HMMA drain)
#pragma unroll
            for (int j = 0; j < 11; j++) Bw[j] = sp[32 + j * 4];
#pragma unroll
            for (int j = 0; j < 4; j++) Sd[j] = seedp[32 + j * 4];
            sp += 32;
            seedp += 32;

            // single epilogue: 8 HMAX2
#pragma unroll
            for (int nt = 0; nt < 4; nt++) {
                mn2[0][0] = __hmax2(mn2[0][0], *(__half2*)&C[0][nt][0]);
                mn2[0][1] = __hmax2(mn2[0][1], *(__half2*)&C[0][nt][1]);
                mn2[1][0] = __hmax2(mn2[1][0], *(__half2*)&C[1][nt][0]);
                mn2[1][1] = __hmax2(mn2[1][1], *(__half2*)&C[1][nt][1]);
            }
        }

        // ---- init barrier before first atomicMin (expected zero wait)
        if (tid == 0) { while (atomicAdd(&g_ictr, 0) < GRID) { } }
        __syncthreads();

        // reduce: max over h2 halves, then over the 4 q-lanes sharing rows
#pragma unroll
        for (int mt = 0; mt < 2; mt++)
#pragma unroll
            for (int h = 0; h < 2; h++) {
                float2 f = __half22float2(mn2[mt][h]);
                float m = fmaxf(f.x, f.y);
                m = fmaxf(m, __shfl_xor_sync(0xFFFFFFFFu, m, 1));
                m = fmaxf(m, __shfl_xor_sync(0xFFFFFFFFu, m, 2));
                if (q == 0) {
                    int kr = wm * 32 + mt * 16 + h * 8 + g;
                    float d2 = fmaf(-2.f, m, s2v[mt][h]);
                    atomicMin(&g_minb[n * KK + kr], __float_as_int(d2));
                }
            }

        js += run;
    }

    // last CTA finalizes: sqrt(min d^2) -> out; reset counters for replay
    __shared__ int lastFlag;
    __threadfence();
    __syncthreads();
    if (tid == 0) lastFlag = (atomicAdd(&g_ctr, 1) == GRID - 1);
    __syncthreads();
    if (lastFlag) {
        __threadfence();
        for (int i = tid; i < NN * KK; i += TMAIN) {
            float d2 = __int_as_float(g_minb[i]);
            out[i] = sqrtf(fmaxf(d2, 0.f));
        }
        __threadfence();
        if (tid == 0) { g_ctr = 0; g_ictr = 0; }
    }
}

// ---------------------------------------------------------------- launch
extern "C" void kernel_launch(void* const* d_in, const int* in_sizes, int n_in,
                              void* d_out, int out_size) {
    const float* x  = (const float*)d_in[0];
    const float* sh = (const float*)d_in[1];
    if (n_in >= 2 && in_sizes[0] == CC * KK * SS && in_sizes[1] == NN * CC * LL) {
        x  = (const float*)d_in[1];
        sh = (const float*)d_in[0];
    }
    main_kernel<<<GRID, TMAIN>>>(x, sh, (float*)d_out);
}